// round 13
// baseline (speedup 1.0000x reference)
#include <cuda_runtime.h>
#include <cuda_bf16.h>
#include <stdint.h>
#include <stddef.h>
#include <math.h>

#define BB   4
#define TT   2048
#define HIDD 1024
#define MM   (BB*TT)      // 8192 tokens
#define NHH  4
#define KDD  512
#define VDD  1024
#define DKK  128
#define DVV  256
#define GLRK 64
#define XPP  256          // padded xp width (160 -> 256)

// ------------------------ scratch (static device globals; no allocs) -----------------
__device__ __align__(256) float g_xp  [(size_t)MM*XPP];
__device__ __align__(256) float g_r   [(size_t)MM*KDD];
__device__ __align__(256) float g_k   [(size_t)MM*KDD];
__device__ __align__(256) float g_ew  [(size_t)MM*KDD];
__device__ __align__(256) float g_wmid[(size_t)MM*128];
__device__ __align__(256) float g_v   [(size_t)MM*VDD];
__device__ __align__(256) float g_sg  [(size_t)MM*VDD];
__device__ __align__(256) float g_c   [(size_t)MM*NHH];
__device__ __align__(256) float g_o   [(size_t)MM*VDD];

// bf16 hi/lo operands for tensor GEMMs
__device__ __align__(256) __nv_bfloat16 g_xl0hi[(size_t)MM*HIDD], g_xl0lo[(size_t)MM*HIDD];
__device__ __align__(256) __nv_bfloat16 g_acthi[(size_t)4*MM*HIDD]; // R,K,V,G lerped acts
__device__ __align__(256) __nv_bfloat16 g_actlo[(size_t)4*MM*HIDD];
__device__ __align__(256) __nv_bfloat16 g_mwhi [(size_t)MM*HIDD],  g_mwlo [(size_t)MM*HIDD];
__device__ __align__(256) __nv_bfloat16 g_gathi[(size_t)MM*VDD];
__device__ __align__(256) __nv_bfloat16 g_gatlo[(size_t)MM*VDD];
__device__ __align__(256) __nv_bfloat16 g_wx0hi[(size_t)XPP*HIDD], g_wx0lo[(size_t)XPP*HIDD];
__device__ __align__(256) __nv_bfloat16 g_ww1hi[(size_t)128*HIDD], g_ww1lo[(size_t)128*HIDD];
__device__ __align__(256) __nv_bfloat16 g_wrhi[(size_t)KDD*HIDD],  g_wrlo[(size_t)KDD*HIDD];
__device__ __align__(256) __nv_bfloat16 g_wkhi[(size_t)KDD*HIDD],  g_wklo[(size_t)KDD*HIDD];
__device__ __align__(256) __nv_bfloat16 g_wvhi[(size_t)VDD*HIDD],  g_wvlo[(size_t)VDD*HIDD];
__device__ __align__(256) __nv_bfloat16 g_wghi[(size_t)VDD*HIDD],  g_wglo[(size_t)VDD*HIDD];
__device__ __align__(256) __nv_bfloat16 g_wohi[(size_t)HIDD*VDD],  g_wolo[(size_t)HIDD*VDD];

// ------------------------ PTX helpers (sm_80-class + f32x2; NO tcgen05) --------------
__device__ __forceinline__ uint32_t s2u(const void* p) {
    uint32_t a;
    asm("{ .reg .u64 t; cvta.to.shared.u64 t, %1; cvt.u32.u64 %0, t; }" : "=r"(a) : "l"(p));
    return a;
}
__device__ __forceinline__ void cpa16(uint32_t s, const void* g) {
    asm volatile("cp.async.cg.shared.global [%0], [%1], 16;" :: "r"(s), "l"(g) : "memory");
}
__device__ __forceinline__ void cpa4(uint32_t s, const void* g) {
    asm volatile("cp.async.ca.shared.global [%0], [%1], 4;" :: "r"(s), "l"(g) : "memory");
}
__device__ __forceinline__ void ldsm_x4(uint32_t& r0, uint32_t& r1, uint32_t& r2, uint32_t& r3,
                                        uint32_t addr) {
    asm volatile("ldmatrix.sync.aligned.m8n8.x4.shared.b16 {%0,%1,%2,%3}, [%4];"
        : "=r"(r0), "=r"(r1), "=r"(r2), "=r"(r3) : "r"(addr));
}
__device__ __forceinline__ void mma16816(float* d, const uint32_t* a, const uint32_t* b) {
    asm volatile("mma.sync.aligned.m16n8k16.row.col.f32.bf16.bf16.f32 "
        "{%0,%1,%2,%3}, {%4,%5,%6,%7}, {%8,%9}, {%0,%1,%2,%3};"
        : "+f"(d[0]), "+f"(d[1]), "+f"(d[2]), "+f"(d[3])
        : "r"(a[0]), "r"(a[1]), "r"(a[2]), "r"(a[3]), "r"(b[0]), "r"(b[1]));
}
// packed f32x2 (baseline PTX on sm_100+)
__device__ __forceinline__ uint64_t pk2(float v) {
    uint64_t r; asm("mov.b64 %0, {%1, %1};" : "=l"(r) : "f"(v)); return r;
}
__device__ __forceinline__ uint64_t fma2(uint64_t a, uint64_t b, uint64_t c) {
    uint64_t d; asm("fma.rn.f32x2 %0, %1, %2, %3;" : "=l"(d) : "l"(a), "l"(b), "l"(c)); return d;
}
__device__ __forceinline__ uint64_t mul2(uint64_t a, uint64_t b) {
    uint64_t d; asm("mul.rn.f32x2 %0, %1, %2;" : "=l"(d) : "l"(a), "l"(b)); return d;
}
__device__ __forceinline__ void upk2(uint64_t v, float& lo, float& hi) {
    asm("mov.b64 {%0, %1}, %2;" : "=f"(lo), "=f"(hi) : "l"(v));
}

// ------------------------ HMMA GEMM: C[M,N] = A[M,K] @ B[N,K]^T ----------------------
#define HT_STRIDE 72
#define HT_TILEB  (128 * HT_STRIDE * 2)
#define HT_STAGEB (4 * HT_TILEB)
#define HT_SMEM   (2 * HT_STAGEB)         // 147456 B

__device__ __forceinline__ void ht_load_chunk(
    uint32_t sb, int c,
    const __nv_bfloat16* Ahi, const __nv_bfloat16* Alo,
    const __nv_bfloat16* Bhi, const __nv_bfloat16* Blo,
    int m0, int n0, int K, int tid)
{
    uint32_t tb = sb + (uint32_t)(c & 1) * HT_STAGEB;
    const __nv_bfloat16* srcs[4] = {Ahi, Alo, Bhi, Blo};
#pragma unroll
    for (int t = 0; t < 4; t++) {
        int rb = (t < 2) ? m0 : n0;
        const __nv_bfloat16* s = srcs[t];
        uint32_t td = tb + t * HT_TILEB;
#pragma unroll
        for (int i = 0; i < 4; i++) {
            int u = tid + i * 256;
            int r = u >> 3, ur = u & 7;
            cpa16(td + (uint32_t)r * (HT_STRIDE * 2) + ur * 16,
                  s + (size_t)(rb + r) * K + c * 64 + ur * 8);
        }
    }
    asm volatile("cp.async.commit_group;" ::: "memory");
}

template<int EPI>   // 0 none, 1 tanh, 3 silu
__global__ __launch_bounds__(256, 1)
void tgemm_kernel(const __nv_bfloat16* __restrict__ Ahi, const __nv_bfloat16* __restrict__ Alo,
                  const __nv_bfloat16* __restrict__ Bhi, const __nv_bfloat16* __restrict__ Blo,
                  float* __restrict__ C, int N, int K)
{
    extern __shared__ __align__(128) char dsm[];
    uint32_t sb = s2u(dsm);
    const int tid = threadIdx.x;
    const int lane = tid & 31;
    const int wid = tid >> 5;
    const int wm = wid >> 2;
    const int wn = wid & 3;
    const int m0 = blockIdx.y * 128;
    const int n0 = blockIdx.x * 128;
    const int NC = K >> 6;

    float acc[4][4][4];
#pragma unroll
    for (int mt = 0; mt < 4; mt++)
#pragma unroll
        for (int nt = 0; nt < 4; nt++)
#pragma unroll
            for (int e = 0; e < 4; e++) acc[mt][nt][e] = 0.f;

    ht_load_chunk(sb, 0, Ahi, Alo, Bhi, Blo, m0, n0, K, tid);

    for (int c = 0; c < NC; c++) {
        if (c + 1 < NC) {
            ht_load_chunk(sb, c + 1, Ahi, Alo, Bhi, Blo, m0, n0, K, tid);
            asm volatile("cp.async.wait_group 1;" ::: "memory");
        } else {
            asm volatile("cp.async.wait_group 0;" ::: "memory");
        }
        __syncthreads();

        uint32_t tb  = sb + (uint32_t)(c & 1) * HT_STAGEB;
        uint32_t sAh = tb;
        uint32_t sAl = tb + HT_TILEB;
        uint32_t sBh = tb + 2 * HT_TILEB;
        uint32_t sBl = tb + 3 * HT_TILEB;

#pragma unroll
        for (int ks = 0; ks < 4; ks++) {
            uint32_t ah[4][4], al[4][4];
            int arow = wm * 64 + (lane & 15);
            int acol = ks * 16 + (lane >> 4) * 8;
#pragma unroll
            for (int mt = 0; mt < 4; mt++) {
                uint32_t off = (uint32_t)((arow + mt * 16) * HT_STRIDE + acol) * 2;
                ldsm_x4(ah[mt][0], ah[mt][1], ah[mt][2], ah[mt][3], sAh + off);
                ldsm_x4(al[mt][0], al[mt][1], al[mt][2], al[mt][3], sAl + off);
            }
            uint32_t bh[4][2], bl[4][2];
#pragma unroll
            for (int pr = 0; pr < 2; pr++) {
                int brow = wn * 32 + pr * 16 + (lane >> 4) * 8 + (lane & 7);
                int bcol = ks * 16 + ((lane >> 3) & 1) * 8;
                uint32_t off = (uint32_t)(brow * HT_STRIDE + bcol) * 2;
                ldsm_x4(bh[pr*2][0], bh[pr*2][1], bh[pr*2+1][0], bh[pr*2+1][1], sBh + off);
                ldsm_x4(bl[pr*2][0], bl[pr*2][1], bl[pr*2+1][0], bl[pr*2+1][1], sBl + off);
            }
#pragma unroll
            for (int mt = 0; mt < 4; mt++)
#pragma unroll
                for (int nt = 0; nt < 4; nt++) {
                    mma16816(acc[mt][nt], ah[mt], bh[nt]);
                    mma16816(acc[mt][nt], ah[mt], bl[nt]);
                    mma16816(acc[mt][nt], al[mt], bh[nt]);
                }
        }
        __syncthreads();
    }

    int gr = lane >> 2, gc = (lane & 3) * 2;
#pragma unroll
    for (int mt = 0; mt < 4; mt++) {
#pragma unroll
        for (int nt = 0; nt < 4; nt++) {
            float* a4 = acc[mt][nt];
            if (EPI == 3) {
#pragma unroll
                for (int e = 0; e < 4; e++) a4[e] = a4[e] / (1.f + expf(-a4[e]));
            } else if (EPI == 1) {
#pragma unroll
                for (int e = 0; e < 4; e++) a4[e] = tanhf(a4[e]);
            }
            int m = m0 + wm * 64 + mt * 16 + gr;
            int n = n0 + wn * 32 + nt * 8 + gc;
            float2 lo2; lo2.x = a4[0]; lo2.y = a4[1];
            float2 hi2; hi2.x = a4[2]; hi2.y = a4[3];
            *(float2*)(C + (size_t)m * N + n)       = lo2;
            *(float2*)(C + (size_t)(m + 8) * N + n) = hi2;
        }
    }
}

// ------------------------ fp32 SIMT SGEMM (ew path only) -----------------------------
template<int EPI>   // 2: exp(-exp)
__global__ __launch_bounds__(256, 2)
void sgemm_kernel(const float* __restrict__ A, int lda,
                  const float* __restrict__ B, int ldb,
                  const float* __restrict__ bias,
                  float* __restrict__ C, int ldc,
                  int M, int N, int K)
{
    __shared__ __align__(16) float As[8][128];
    __shared__ __align__(16) float Bs[8][128];
    int tid = threadIdx.x;
    int m0 = blockIdx.y * 128;
    int n0 = blockIdx.x * 128;
    int lr = tid >> 1;
    int lk = (tid & 1) * 4;
    int tx = tid & 15, ty = tid >> 4;

    float acc[8][8];
#pragma unroll
    for (int i = 0; i < 8; i++)
#pragma unroll
        for (int j = 0; j < 8; j++) acc[i][j] = 0.f;

    const float* Ap = A + (size_t)(m0 + lr) * lda + lk;
    int brow = n0 + lr;
    const float* Bp = B + (size_t)brow * ldb + lk;
    bool bvalid = (brow < N);

    for (int kb = 0; kb < K; kb += 8) {
        float4 av = *(const float4*)(Ap + kb);
        float4 bv = bvalid ? *(const float4*)(Bp + kb) : make_float4(0.f, 0.f, 0.f, 0.f);
        As[lk+0][lr] = av.x; As[lk+1][lr] = av.y; As[lk+2][lr] = av.z; As[lk+3][lr] = av.w;
        Bs[lk+0][lr] = bv.x; Bs[lk+1][lr] = bv.y; Bs[lk+2][lr] = bv.z; Bs[lk+3][lr] = bv.w;
        __syncthreads();
#pragma unroll
        for (int kk = 0; kk < 8; kk++) {
            float4 a0 = *(const float4*)&As[kk][ty*8];
            float4 a1 = *(const float4*)&As[kk][ty*8+4];
            float4 b0 = *(const float4*)&Bs[kk][tx*8];
            float4 b1 = *(const float4*)&Bs[kk][tx*8+4];
            float a[8] = {a0.x,a0.y,a0.z,a0.w,a1.x,a1.y,a1.z,a1.w};
            float b[8] = {b0.x,b0.y,b0.z,b0.w,b1.x,b1.y,b1.z,b1.w};
#pragma unroll
            for (int i = 0; i < 8; i++)
#pragma unroll
                for (int j = 0; j < 8; j++) acc[i][j] += a[i] * b[j];
        }
        __syncthreads();
    }

#pragma unroll
    for (int i = 0; i < 8; i++) {
        int m = m0 + ty * 8 + i;
#pragma unroll
        for (int j = 0; j < 8; j++) {
            int n = n0 + tx * 8 + j;
            if (n < N) {
                float val = acc[i][j];
                if (bias) val += bias[n];
                if (EPI == 2) val = expf(-expf(val));
                C[(size_t)m * ldc + n] = val;
            }
        }
    }
}

// ------------------------ fused mus (5-slot K=32 GEMM) + lerp + bf16 split ----------
#define MUS_SMEM (2 * 160 * 128 * 4)
__global__ __launch_bounds__(256, 1)
void musfuse_kernel(const float* __restrict__ hs, const float* __restrict__ W_x2,
                    const float* __restrict__ x_bias)
{
    extern __shared__ __align__(16) float sm[];
    float* xpT = sm;
    float* wT  = sm + 160 * 128;
    int tid = threadIdx.x;
    int n0 = blockIdx.x * 128;
    int m0 = blockIdx.y * 128;

    for (int u = tid; u < 128 * 40; u += 256) {
        int r = u / 40, q = u % 40;
        float4 v = *(const float4*)(g_xp + (size_t)(m0 + r) * XPP + q * 4);
        xpT[(q*4+0)*128 + r] = v.x; xpT[(q*4+1)*128 + r] = v.y;
        xpT[(q*4+2)*128 + r] = v.z; xpT[(q*4+3)*128 + r] = v.w;
        float4 w = *(const float4*)(W_x2 + (size_t)(n0 + r) * 160 + q * 4);
        wT[(q*4+0)*128 + r] = w.x; wT[(q*4+1)*128 + r] = w.y;
        wT[(q*4+2)*128 + r] = w.z; wT[(q*4+3)*128 + r] = w.w;
    }
    __syncthreads();

    int tx = tid & 15, ty = tid >> 4;
    int col0 = n0 + tx * 8;
    const size_t AS = (size_t)MM * HIDD;

#pragma unroll
    for (int s = 0; s < 5; s++) {
        float acc[8][8];
#pragma unroll
        for (int i = 0; i < 8; i++)
#pragma unroll
            for (int j = 0; j < 8; j++) acc[i][j] = 0.f;

        for (int k = 0; k < 32; k++) {
            int kk = s * 32 + k;
            float4 a0 = *(const float4*)&xpT[kk*128 + ty*8];
            float4 a1 = *(const float4*)&xpT[kk*128 + ty*8 + 4];
            float4 b0 = *(const float4*)&wT [kk*128 + tx*8];
            float4 b1 = *(const float4*)&wT [kk*128 + tx*8 + 4];
            float a[8] = {a0.x,a0.y,a0.z,a0.w,a1.x,a1.y,a1.z,a1.w};
            float b[8] = {b0.x,b0.y,b0.z,b0.w,b1.x,b1.y,b1.z,b1.w};
#pragma unroll
            for (int i = 0; i < 8; i++)
#pragma unroll
                for (int j = 0; j < 8; j++) acc[i][j] += a[i] * b[j];
        }

        float4 bi0 = *(const float4*)(x_bias + s * HIDD + col0);
        float4 bi1 = *(const float4*)(x_bias + s * HIDD + col0 + 4);
        float bias8[8] = {bi0.x,bi0.y,bi0.z,bi0.w,bi1.x,bi1.y,bi1.z,bi1.w};

#pragma unroll
        for (int i = 0; i < 8; i++) {
            int m = m0 + ty * 8 + i;
            int t = m & (TT - 1);
            const float* xr = hs + (size_t)m * HIDD + col0;
            float4 x0 = *(const float4*)xr;
            float4 x1 = *(const float4*)(xr + 4);
            float4 p0 = make_float4(0.f,0.f,0.f,0.f), p1 = p0;
            if (t > 0) {
                p0 = *(const float4*)(xr - HIDD);
                p1 = *(const float4*)(xr - HIDD + 4);
            }
            float xv[8] = {x0.x,x0.y,x0.z,x0.w,x1.x,x1.y,x1.z,x1.w};
            float pv[8] = {p0.x,p0.y,p0.z,p0.w,p1.x,p1.y,p1.z,p1.w};
            float lv[8];
#pragma unroll
            for (int j = 0; j < 8; j++) {
                float mu = acc[i][j] + bias8[j];
                lv[j] = xv[j] + (pv[j] - xv[j]) * mu;
            }
            size_t base = (size_t)m * HIDD + col0;
            __nv_bfloat16 h8[8], l8[8];
#pragma unroll
            for (int j = 0; j < 8; j++) {
                __nv_bfloat16 hh = __float2bfloat16(lv[j]);
                h8[j] = hh;
                l8[j] = __float2bfloat16(lv[j] - __bfloat162float(hh));
            }
            if (s == 1) {
                *(uint4*)(g_mwhi + base) = *(uint4*)h8;
                *(uint4*)(g_mwlo + base) = *(uint4*)l8;
            } else {
                int a = (s == 0) ? 0 : (s - 1);
                *(uint4*)(g_acthi + a * AS + base) = *(uint4*)h8;
                *(uint4*)(g_actlo + a * AS + base) = *(uint4*)l8;
            }
        }
    }
}

// ------------------------ fused prep: lerp0 + all weight hi/lo conversions -----------
// flat-index regions (element counts):
//  [0, 8388608)          lerp0 -> g_xl0hi/lo
//  [.., +262144)         W_x0 pad(160->256 rows) -> g_wx0
//  [.., +131072)         W_w1 pad(64->128 rows)  -> g_ww1
//  [.., +524288)         W_r -> g_wr
//  [.., +524288)         W_k -> g_wk
//  [.., +1048576)        W_v -> g_wv
//  [.., +1048576)        W_g -> g_wg
//  [.., +1048576)        W_o -> g_wo
#define PRE_L0 (MM*HIDD)
#define PRE_L1 (PRE_L0 + XPP*HIDD)
#define PRE_L2 (PRE_L1 + 128*HIDD)
#define PRE_L3 (PRE_L2 + KDD*HIDD)
#define PRE_L4 (PRE_L3 + KDD*HIDD)
#define PRE_L5 (PRE_L4 + VDD*HIDD)
#define PRE_L6 (PRE_L5 + VDD*HIDD)
#define PRE_L7 (PRE_L6 + HIDD*VDD)
#define PRE_TOT PRE_L7

__device__ __forceinline__ void hilo_store(float x, __nv_bfloat16* hi, __nv_bfloat16* lo, int i)
{
    __nv_bfloat16 h = __float2bfloat16(x);
    hi[i] = h;
    lo[i] = __float2bfloat16(x - __bfloat162float(h));
}

__global__ void prep_kernel(const float* __restrict__ hs, const float* __restrict__ mu0,
                            const float* __restrict__ W_x0, const float* __restrict__ W_w1,
                            const float* __restrict__ W_r,  const float* __restrict__ W_k,
                            const float* __restrict__ W_v,  const float* __restrict__ W_g,
                            const float* __restrict__ W_o)
{
    int i = blockIdx.x * 256 + threadIdx.x;
    if (i < PRE_L0) {
        int m = i >> 10, h = i & 1023;
        int t = m & (TT - 1);
        float x = hs[i];
        float xp = (t > 0) ? hs[i - HIDD] : 0.f;
        float v = x + (xp - x) * mu0[h];
        hilo_store(v, g_xl0hi, g_xl0lo, i);
    } else if (i < PRE_L1) {
        int j = i - PRE_L0;
        float x = ((j >> 10) < 160) ? W_x0[j] : 0.f;
        hilo_store(x, g_wx0hi, g_wx0lo, j);
    } else if (i < PRE_L2) {
        int j = i - PRE_L1;
        float x = ((j >> 10) < GLRK) ? W_w1[j] : 0.f;
        hilo_store(x, g_ww1hi, g_ww1lo, j);
    } else if (i < PRE_L3) {
        int j = i - PRE_L2;  hilo_store(W_r[j], g_wrhi, g_wrlo, j);
    } else if (i < PRE_L4) {
        int j = i - PRE_L3;  hilo_store(W_k[j], g_wkhi, g_wklo, j);
    } else if (i < PRE_L5) {
        int j = i - PRE_L4;  hilo_store(W_v[j], g_wvhi, g_wvlo, j);
    } else if (i < PRE_L6) {
        int j = i - PRE_L5;  hilo_store(W_g[j], g_wghi, g_wglo, j);
    } else {
        int j = i - PRE_L6;  hilo_store(W_o[j], g_wohi, g_wolo, j);
    }
}

__global__ void cterm_kernel(const float* __restrict__ bonus)
{
    int m = blockIdx.x;
    int h = threadIdx.x >> 5, lane = threadIdx.x & 31;
    size_t base = (size_t)m * KDD + h * DKK;
    float s = 0.f;
#pragma unroll
    for (int q = 0; q < 4; q++) {
        int kk = lane + q * 32;
        s += g_r[base + kk] * bonus[h * DKK + kk] * g_k[base + kk];
    }
#pragma unroll
    for (int off = 16; off > 0; off >>= 1) s += __shfl_xor_sync(0xFFFFFFFFu, s, off);
    if (lane == 0) g_c[(size_t)m * NHH + h] = s;
}

// ------------------------ recurrent scan: cp.async ring + f32x2 ----------------------
#define SC_SLOT 432

__device__ __forceinline__ void scan_issue(uint32_t sbase, int bi, int b, int h,
                                           int vcol, int tid)
{
#pragma unroll
    for (int i = 0; i < 2; i++) {
        int u = tid + i * 256;
        if (u < 420) {
            int step = u / 105, w = u % 105;
            uint32_t st = sbase + (uint32_t)(((bi & 3) * 4 + step) * SC_SLOT) * 4;
            size_t mb = (size_t)(b * TT + bi * 4 + step);
            if (w < 96) {
                int arr = w >> 5, idx = (w & 31) * 4;
                const float* src = (arr == 0 ? g_r : arr == 1 ? g_k : g_ew)
                                 + mb * KDD + h * DKK + idx;
                cpa16(st + (uint32_t)(arr * 128 + idx) * 4, src);
            } else if (w < 104) {
                int idx = (w - 96) * 4;
                cpa16(st + (uint32_t)(384 + idx) * 4, g_v + mb * VDD + vcol + idx);
            } else {
                cpa4(st + 416u * 4, g_c + mb * NHH + h);
            }
        }
    }
    asm volatile("cp.async.commit_group;" ::: "memory");
}

__global__ __launch_bounds__(256, 1)
void scan_kernel()
{
    int ch = blockIdx.x, h = blockIdx.y, b = blockIdx.z;
    int tid = threadIdx.x;
    int kg = tid & 7, jl = tid >> 3;
    int vcol = h * DVV + ch * 32;

    __shared__ __align__(16) float ssc[16 * SC_SLOT];
    uint32_t sbase = s2u(ssc);

    uint64_t S2[8];
#pragma unroll
    for (int i = 0; i < 8; i++) S2[i] = 0ull;

    const int NBATCH = TT / 4;   // 512
    scan_issue(sbase, 0, b, h, vcol, tid);
    scan_issue(sbase, 1, b, h, vcol, tid);
    scan_issue(sbase, 2, b, h, vcol, tid);

    for (int bi = 0; bi < NBATCH; bi++) {
        if (bi < NBATCH - 2)      asm volatile("cp.async.wait_group 2;" ::: "memory");
        else if (bi == NBATCH - 2) asm volatile("cp.async.wait_group 1;" ::: "memory");
        else                       asm volatile("cp.async.wait_group 0;" ::: "memory");
        __syncthreads();

#pragma unroll
        for (int s = 0; s < 4; s++) {
            const float* stg = ssc + ((bi & 3) * 4 + s) * SC_SLOT;
            float vj = stg[384 + jl];
            float cc = stg[416];
            uint64_t vj2 = pk2(vj);
            const ulonglong2* r2 = (const ulonglong2*)(stg + kg * 16);
            const ulonglong2* k2 = (const ulonglong2*)(stg + 128 + kg * 16);
            const ulonglong2* e2 = (const ulonglong2*)(stg + 256 + kg * 16);
            uint64_t acc2 = 0ull;
#pragma unroll
            for (int q = 0; q < 4; q++) {
                ulonglong2 rq = r2[q], kq = k2[q], eq = e2[q];
                acc2 = fma2(rq.x, S2[q*2+0], acc2);
                acc2 = fma2(rq.y, S2[q*2+1], acc2);
                S2[q*2+0] = fma2(eq.x, S2[q*2+0], mul2(kq.x, vj2));
                S2[q*2+1] = fma2(eq.y, S2[q*2+1], mul2(kq.y, vj2));
            }
            float a0, a1;
            upk2(acc2, a0, a1);
            float acc = a0 + a1;
            acc += __shfl_xor_sync(0xFFFFFFFFu, acc, 1);
            acc += __shfl_xor_sync(0xFFFFFFFFu, acc, 2);
            acc += __shfl_xor_sync(0xFFFFFFFFu, acc, 4);
            if (kg == 0) {
                int t = bi * 4 + s;
                g_o[(size_t)(b * TT + t) * VDD + vcol + jl] = acc + cc * vj;
            }
        }
        if (bi + 3 < NBATCH)
            scan_issue(sbase, bi + 3, b, h, vcol, tid);
    }
}

// ------------------------ groupnorm + gate + bf16 split ------------------------------
__global__ void post_kernel(const float* __restrict__ gnw, const float* __restrict__ gnb)
{
    int m = blockIdx.x, h = blockIdx.y;
    int j = threadIdx.x;  // 256
    __shared__ float red[256];
    size_t base = (size_t)m * VDD + h * DVV;
    float val = g_o[base + j];

    red[j] = val; __syncthreads();
    for (int s = 128; s > 0; s >>= 1) { if (j < s) red[j] += red[j + s]; __syncthreads(); }
    float mean = red[0] * (1.f / 256.f);
    __syncthreads();
    float d = val - mean;
    red[j] = d * d; __syncthreads();
    for (int s = 128; s > 0; s >>= 1) { if (j < s) red[j] += red[j + s]; __syncthreads(); }
    float var = red[0] * (1.f / 256.f);

    float nv = d * rsqrtf(var + 1e-5f);
    int col = h * DVV + j;
    float gv = (nv * gnw[col] + gnb[col]) * g_sg[base + j];
    __nv_bfloat16 hh = __float2bfloat16(gv);
    g_gathi[base + j] = hh;
    g_gatlo[base + j] = __float2bfloat16(gv - __bfloat162float(hh));
}

// ------------------------ host launch ------------------------------------------------
extern "C" void kernel_launch(void* const* d_in, const int* in_sizes, int n_in,
                              void* d_out, int out_size)
{
    const float* hs    = (const float*)d_in[0];
    const float* mu0   = (const float*)d_in[1];
    const float* W_x0  = (const float*)d_in[2];
    const float* W_x2  = (const float*)d_in[3];
    const float* x_bias= (const float*)d_in[4];
    const float* W_r   = (const float*)d_in[5];
    const float* W_w1  = (const float*)d_in[6];
    const float* W_w2  = (const float*)d_in[7];
    const float* b_w2  = (const float*)d_in[8];
    const float* W_k   = (const float*)d_in[9];
    const float* W_v   = (const float*)d_in[10];
    const float* W_g   = (const float*)d_in[11];
    const float* bonus = (const float*)d_in[12];
    const float* gnw   = (const float*)d_in[13];
    const float* gnb   = (const float*)d_in[14];
    const float* W_o   = (const float*)d_in[15];
    float* out = (float*)d_out;

    float *xp, *r_, *k_, *ew, *wmid, *v_, *sg;
    cudaGetSymbolAddress((void**)&xp,   g_xp);
    cudaGetSymbolAddress((void**)&r_,   g_r);
    cudaGetSymbolAddress((void**)&k_,   g_k);
    cudaGetSymbolAddress((void**)&ew,   g_ew);
    cudaGetSymbolAddress((void**)&wmid, g_wmid);
    cudaGetSymbolAddress((void**)&v_,   g_v);
    cudaGetSymbolAddress((void**)&sg,   g_sg);

    __nv_bfloat16 *xl0h, *xl0l, *acthi, *actlo, *mwh, *mwl, *gathi, *gatlo;
    __nv_bfloat16 *wx0h, *wx0l, *ww1h, *ww1l;
    __nv_bfloat16 *wrh, *wrl, *wkh, *wkl, *wvh, *wvl, *wgh, *wgl, *woh, *wol;
    cudaGetSymbolAddress((void**)&xl0h, g_xl0hi); cudaGetSymbolAddress((void**)&xl0l, g_xl0lo);
    cudaGetSymbolAddress((void**)&acthi, g_acthi);
    cudaGetSymbolAddress((void**)&actlo, g_actlo);
    cudaGetSymbolAddress((void**)&mwh, g_mwhi);   cudaGetSymbolAddress((void**)&mwl, g_mwlo);
    cudaGetSymbolAddress((void**)&gathi, g_gathi);
    cudaGetSymbolAddress((void**)&gatlo, g_gatlo);
    cudaGetSymbolAddress((void**)&wx0h, g_wx0hi); cudaGetSymbolAddress((void**)&wx0l, g_wx0lo);
    cudaGetSymbolAddress((void**)&ww1h, g_ww1hi); cudaGetSymbolAddress((void**)&ww1l, g_ww1lo);
    cudaGetSymbolAddress((void**)&wrh, g_wrhi);  cudaGetSymbolAddress((void**)&wrl, g_wrlo);
    cudaGetSymbolAddress((void**)&wkh, g_wkhi);  cudaGetSymbolAddress((void**)&wkl, g_wklo);
    cudaGetSymbolAddress((void**)&wvh, g_wvhi);  cudaGetSymbolAddress((void**)&wvl, g_wvlo);
    cudaGetSymbolAddress((void**)&wgh, g_wghi);  cudaGetSymbolAddress((void**)&wgl, g_wglo);
    cudaGetSymbolAddress((void**)&woh, g_wohi);  cudaGetSymbolAddress((void**)&wol, g_wolo);

    cudaFuncSetAttribute(tgemm_kernel<0>, cudaFuncAttributeMaxDynamicSharedMemorySize, HT_SMEM);
    cudaFuncSetAttribute(tgemm_kernel<1>, cudaFuncAttributeMaxDynamicSharedMemorySize, HT_SMEM);
    cudaFuncSetAttribute(tgemm_kernel<3>, cudaFuncAttributeMaxDynamicSharedMemorySize, HT_SMEM);
    cudaFuncSetAttribute(musfuse_kernel,  cudaFuncAttributeMaxDynamicSharedMemorySize, MUS_SMEM);

    // launch 0: fused prep (lerp0 + all weight conversions)
    prep_kernel<<<PRE_TOT/256, 256>>>(hs, mu0, W_x0, W_w1, W_r, W_k, W_v, W_g, W_o);

    // launch 1: xp = tanh(xl0 @ W_x0^T)  (HMMA, N padded to 256)
    tgemm_kernel<1><<<dim3(XPP/128, MM/128), 256, HT_SMEM>>>(xl0h, xl0l, wx0h, wx0l, xp, XPP, HIDD);

    // launch 2: fused 5-slot mus GEMM + lerp + bf16 hi/lo split
    musfuse_kernel<<<dim3(8, MM/128), 256, MUS_SMEM>>>(hs, W_x2, x_bias);

    // launch 3: wmid = tanh(musW @ W_w1^T) (HMMA, N padded to 128)
    tgemm_kernel<1><<<dim3(1, MM/128), 256, HT_SMEM>>>(mwh, mwl, ww1h, ww1l, wmid, 128, HIDD);

    // launch 4: ew = exp(-exp(wmid @ W_w2^T + b)) (SIMT, K=64)
    sgemm_kernel<2><<<dim3(4, MM/128), 256>>>(wmid, 128, W_w2, GLRK, b_w2, ew, KDD, MM, KDD, GLRK);

    // launch 5 (ncu capture target): r projection
    const size_t AS = (size_t)MM * HIDD;
    tgemm_kernel<0><<<dim3(KDD/128, MM/128), 256, HT_SMEM>>>(acthi + 0*AS, actlo + 0*AS, wrh, wrl, r_, KDD, HIDD);
    tgemm_kernel<0><<<dim3(KDD/128, MM/128), 256, HT_SMEM>>>(acthi + 1*AS, actlo + 1*AS, wkh, wkl, k_, KDD, HIDD);
    tgemm_kernel<0><<<dim3(VDD/128, MM/128), 256, HT_SMEM>>>(acthi + 2*AS, actlo + 2*AS, wvh, wvl, v_, VDD, HIDD);
    tgemm_kernel<3><<<dim3(VDD/128, MM/128), 256, HT_SMEM>>>(acthi + 3*AS, actlo + 3*AS, wgh, wgl, sg, VDD, HIDD);

    // bonus scalar
    cterm_kernel<<<MM, 128>>>(bonus);

    // recurrent scan (cp.async ring, f32x2)
    scan_kernel<<<dim3(8, NHH, BB), 256>>>();

    // groupnorm + silu gate -> bf16 hi/lo
    post_kernel<<<dim3(MM, NHH), 256>>>(gnw, gnb);

    // out = gated @ W_o^T
    tgemm_kernel<0><<<dim3(HIDD/128, MM/128), 256, HT_SMEM>>>(gathi, gatlo, woh, wol, out, HIDD, VDD);
}

// round 17
// speedup vs baseline: 1.6031x; 1.6031x over previous
#include <cuda_runtime.h>
#include <cuda_bf16.h>
#include <stdint.h>
#include <stddef.h>
#include <math.h>

#define BB   4
#define TT   2048
#define HIDD 1024
#define MM   (BB*TT)      // 8192 tokens
#define NHH  4
#define KDD  512
#define VDD  1024
#define DKK  128
#define DVV  256
#define GLRK 64
#define XPP  256          // padded xp width (160 -> 256)

// ------------------------ scratch (static device globals; no allocs) -----------------
__device__ __align__(256) float g_xp  [(size_t)MM*XPP];
__device__ __align__(256) float g_r   [(size_t)MM*KDD];
__device__ __align__(256) float g_k   [(size_t)MM*KDD];
__device__ __align__(256) float g_ew  [(size_t)MM*KDD];
__device__ __align__(256) float g_wmid[(size_t)MM*128];
__device__ __align__(256) float g_v   [(size_t)MM*VDD];
__device__ __align__(256) float g_sg  [(size_t)MM*VDD];
__device__ __align__(256) float g_c   [(size_t)MM*NHH];
__device__ __align__(256) float g_o   [(size_t)MM*VDD];

// bf16 hi/lo operands for tensor GEMMs
__device__ __align__(256) __nv_bfloat16 g_xl0hi[(size_t)MM*HIDD], g_xl0lo[(size_t)MM*HIDD];
__device__ __align__(256) __nv_bfloat16 g_acthi[(size_t)4*MM*HIDD]; // R,K,V,G lerped acts
__device__ __align__(256) __nv_bfloat16 g_actlo[(size_t)4*MM*HIDD];
__device__ __align__(256) __nv_bfloat16 g_mwhi [(size_t)MM*HIDD],  g_mwlo [(size_t)MM*HIDD];
__device__ __align__(256) __nv_bfloat16 g_gathi[(size_t)MM*VDD];
__device__ __align__(256) __nv_bfloat16 g_gatlo[(size_t)MM*VDD];
__device__ __align__(256) __nv_bfloat16 g_wx0hi[(size_t)XPP*HIDD], g_wx0lo[(size_t)XPP*HIDD];
__device__ __align__(256) __nv_bfloat16 g_ww1hi[(size_t)128*HIDD], g_ww1lo[(size_t)128*HIDD];
__device__ __align__(256) __nv_bfloat16 g_wrhi[(size_t)KDD*HIDD],  g_wrlo[(size_t)KDD*HIDD];
__device__ __align__(256) __nv_bfloat16 g_wkhi[(size_t)KDD*HIDD],  g_wklo[(size_t)KDD*HIDD];
__device__ __align__(256) __nv_bfloat16 g_wvhi[(size_t)VDD*HIDD],  g_wvlo[(size_t)VDD*HIDD];
__device__ __align__(256) __nv_bfloat16 g_wghi[(size_t)VDD*HIDD],  g_wglo[(size_t)VDD*HIDD];
__device__ __align__(256) __nv_bfloat16 g_wohi[(size_t)HIDD*VDD],  g_wolo[(size_t)HIDD*VDD];

// ------------------------ PTX helpers (sm_80-class only; NO tcgen05) -----------------
__device__ __forceinline__ uint32_t s2u(const void* p) {
    uint32_t a;
    asm("{ .reg .u64 t; cvta.to.shared.u64 t, %1; cvt.u32.u64 %0, t; }" : "=r"(a) : "l"(p));
    return a;
}
__device__ __forceinline__ void cpa16(uint32_t s, const void* g) {
    asm volatile("cp.async.cg.shared.global [%0], [%1], 16;" :: "r"(s), "l"(g) : "memory");
}
__device__ __forceinline__ void cpa4(uint32_t s, const void* g) {
    asm volatile("cp.async.ca.shared.global [%0], [%1], 4;" :: "r"(s), "l"(g) : "memory");
}
__device__ __forceinline__ void ldsm_x4(uint32_t& r0, uint32_t& r1, uint32_t& r2, uint32_t& r3,
                                        uint32_t addr) {
    asm volatile("ldmatrix.sync.aligned.m8n8.x4.shared.b16 {%0,%1,%2,%3}, [%4];"
        : "=r"(r0), "=r"(r1), "=r"(r2), "=r"(r3) : "r"(addr));
}
__device__ __forceinline__ void mma16816(float* d, const uint32_t* a, const uint32_t* b) {
    asm volatile("mma.sync.aligned.m16n8k16.row.col.f32.bf16.bf16.f32 "
        "{%0,%1,%2,%3}, {%4,%5,%6,%7}, {%8,%9}, {%0,%1,%2,%3};"
        : "+f"(d[0]), "+f"(d[1]), "+f"(d[2]), "+f"(d[3])
        : "r"(a[0]), "r"(a[1]), "r"(a[2]), "r"(a[3]), "r"(b[0]), "r"(b[1]));
}

// ------------------------ HMMA GEMM: C[M,N] = A[M,K] @ B[N,K]^T ----------------------
#define HT_STRIDE 72
#define HT_TILEB  (128 * HT_STRIDE * 2)
#define HT_STAGEB (4 * HT_TILEB)
#define HT_SMEM   (2 * HT_STAGEB)         // 147456 B

__device__ __forceinline__ void ht_load_chunk(
    uint32_t sb, int c,
    const __nv_bfloat16* Ahi, const __nv_bfloat16* Alo,
    const __nv_bfloat16* Bhi, const __nv_bfloat16* Blo,
    int m0, int n0, int K, int tid)
{
    uint32_t tb = sb + (uint32_t)(c & 1) * HT_STAGEB;
    const __nv_bfloat16* srcs[4] = {Ahi, Alo, Bhi, Blo};
#pragma unroll
    for (int t = 0; t < 4; t++) {
        int rb = (t < 2) ? m0 : n0;
        const __nv_bfloat16* s = srcs[t];
        uint32_t td = tb + t * HT_TILEB;
#pragma unroll
        for (int i = 0; i < 4; i++) {
            int u = tid + i * 256;
            int r = u >> 3, ur = u & 7;
            cpa16(td + (uint32_t)r * (HT_STRIDE * 2) + ur * 16,
                  s + (size_t)(rb + r) * K + c * 64 + ur * 8);
        }
    }
    asm volatile("cp.async.commit_group;" ::: "memory");
}

template<int EPI>   // 0 none, 1 tanh, 3 silu
__global__ __launch_bounds__(256, 1)
void tgemm_kernel(const __nv_bfloat16* __restrict__ Ahi, const __nv_bfloat16* __restrict__ Alo,
                  const __nv_bfloat16* __restrict__ Bhi, const __nv_bfloat16* __restrict__ Blo,
                  float* __restrict__ C, int N, int K)
{
    extern __shared__ __align__(128) char dsm[];
    uint32_t sb = s2u(dsm);
    const int tid = threadIdx.x;
    const int lane = tid & 31;
    const int wid = tid >> 5;
    const int wm = wid >> 2;
    const int wn = wid & 3;
    const int m0 = blockIdx.y * 128;
    const int n0 = blockIdx.x * 128;
    const int NC = K >> 6;

    float acc[4][4][4];
#pragma unroll
    for (int mt = 0; mt < 4; mt++)
#pragma unroll
        for (int nt = 0; nt < 4; nt++)
#pragma unroll
            for (int e = 0; e < 4; e++) acc[mt][nt][e] = 0.f;

    ht_load_chunk(sb, 0, Ahi, Alo, Bhi, Blo, m0, n0, K, tid);

    for (int c = 0; c < NC; c++) {
        if (c + 1 < NC) {
            ht_load_chunk(sb, c + 1, Ahi, Alo, Bhi, Blo, m0, n0, K, tid);
            asm volatile("cp.async.wait_group 1;" ::: "memory");
        } else {
            asm volatile("cp.async.wait_group 0;" ::: "memory");
        }
        __syncthreads();

        uint32_t tb  = sb + (uint32_t)(c & 1) * HT_STAGEB;
        uint32_t sAh = tb;
        uint32_t sAl = tb + HT_TILEB;
        uint32_t sBh = tb + 2 * HT_TILEB;
        uint32_t sBl = tb + 3 * HT_TILEB;

#pragma unroll
        for (int ks = 0; ks < 4; ks++) {
            uint32_t ah[4][4], al[4][4];
            int arow = wm * 64 + (lane & 15);
            int acol = ks * 16 + (lane >> 4) * 8;
#pragma unroll
            for (int mt = 0; mt < 4; mt++) {
                uint32_t off = (uint32_t)((arow + mt * 16) * HT_STRIDE + acol) * 2;
                ldsm_x4(ah[mt][0], ah[mt][1], ah[mt][2], ah[mt][3], sAh + off);
                ldsm_x4(al[mt][0], al[mt][1], al[mt][2], al[mt][3], sAl + off);
            }
            uint32_t bh[4][2], bl[4][2];
#pragma unroll
            for (int pr = 0; pr < 2; pr++) {
                int brow = wn * 32 + pr * 16 + (lane >> 4) * 8 + (lane & 7);
                int bcol = ks * 16 + ((lane >> 3) & 1) * 8;
                uint32_t off = (uint32_t)(brow * HT_STRIDE + bcol) * 2;
                ldsm_x4(bh[pr*2][0], bh[pr*2][1], bh[pr*2+1][0], bh[pr*2+1][1], sBh + off);
                ldsm_x4(bl[pr*2][0], bl[pr*2][1], bl[pr*2+1][0], bl[pr*2+1][1], sBl + off);
            }
#pragma unroll
            for (int mt = 0; mt < 4; mt++)
#pragma unroll
                for (int nt = 0; nt < 4; nt++) {
                    mma16816(acc[mt][nt], ah[mt], bh[nt]);
                    mma16816(acc[mt][nt], ah[mt], bl[nt]);
                    mma16816(acc[mt][nt], al[mt], bh[nt]);
                }
        }
        __syncthreads();
    }

    int gr = lane >> 2, gc = (lane & 3) * 2;
#pragma unroll
    for (int mt = 0; mt < 4; mt++) {
#pragma unroll
        for (int nt = 0; nt < 4; nt++) {
            float* a4 = acc[mt][nt];
            if (EPI == 3) {
#pragma unroll
                for (int e = 0; e < 4; e++) a4[e] = a4[e] / (1.f + expf(-a4[e]));
            } else if (EPI == 1) {
#pragma unroll
                for (int e = 0; e < 4; e++) a4[e] = tanhf(a4[e]);
            }
            int m = m0 + wm * 64 + mt * 16 + gr;
            int n = n0 + wn * 32 + nt * 8 + gc;
            float2 lo2; lo2.x = a4[0]; lo2.y = a4[1];
            float2 hi2; hi2.x = a4[2]; hi2.y = a4[3];
            *(float2*)(C + (size_t)m * N + n)       = lo2;
            *(float2*)(C + (size_t)(m + 8) * N + n) = hi2;
        }
    }
}

// ------------------------ fp32 SIMT SGEMM (ew path only) -----------------------------
template<int EPI>   // 2: exp(-exp)
__global__ __launch_bounds__(256, 2)
void sgemm_kernel(const float* __restrict__ A, int lda,
                  const float* __restrict__ B, int ldb,
                  const float* __restrict__ bias,
                  float* __restrict__ C, int ldc,
                  int M, int N, int K)
{
    __shared__ __align__(16) float As[8][128];
    __shared__ __align__(16) float Bs[8][128];
    int tid = threadIdx.x;
    int m0 = blockIdx.y * 128;
    int n0 = blockIdx.x * 128;
    int lr = tid >> 1;
    int lk = (tid & 1) * 4;
    int tx = tid & 15, ty = tid >> 4;

    float acc[8][8];
#pragma unroll
    for (int i = 0; i < 8; i++)
#pragma unroll
        for (int j = 0; j < 8; j++) acc[i][j] = 0.f;

    const float* Ap = A + (size_t)(m0 + lr) * lda + lk;
    int brow = n0 + lr;
    const float* Bp = B + (size_t)brow * ldb + lk;
    bool bvalid = (brow < N);

    for (int kb = 0; kb < K; kb += 8) {
        float4 av = *(const float4*)(Ap + kb);
        float4 bv = bvalid ? *(const float4*)(Bp + kb) : make_float4(0.f, 0.f, 0.f, 0.f);
        As[lk+0][lr] = av.x; As[lk+1][lr] = av.y; As[lk+2][lr] = av.z; As[lk+3][lr] = av.w;
        Bs[lk+0][lr] = bv.x; Bs[lk+1][lr] = bv.y; Bs[lk+2][lr] = bv.z; Bs[lk+3][lr] = bv.w;
        __syncthreads();
#pragma unroll
        for (int kk = 0; kk < 8; kk++) {
            float4 a0 = *(const float4*)&As[kk][ty*8];
            float4 a1 = *(const float4*)&As[kk][ty*8+4];
            float4 b0 = *(const float4*)&Bs[kk][tx*8];
            float4 b1 = *(const float4*)&Bs[kk][tx*8+4];
            float a[8] = {a0.x,a0.y,a0.z,a0.w,a1.x,a1.y,a1.z,a1.w};
            float b[8] = {b0.x,b0.y,b0.z,b0.w,b1.x,b1.y,b1.z,b1.w};
#pragma unroll
            for (int i = 0; i < 8; i++)
#pragma unroll
                for (int j = 0; j < 8; j++) acc[i][j] += a[i] * b[j];
        }
        __syncthreads();
    }

#pragma unroll
    for (int i = 0; i < 8; i++) {
        int m = m0 + ty * 8 + i;
#pragma unroll
        for (int j = 0; j < 8; j++) {
            int n = n0 + tx * 8 + j;
            if (n < N) {
                float val = acc[i][j];
                if (bias) val += bias[n];
                if (EPI == 2) val = expf(-expf(val));
                C[(size_t)m * ldc + n] = val;
            }
        }
    }
}

// ------------------------ fused mus (5-slot K=32 GEMM) + lerp + bf16 split ----------
#define MUS_SMEM (2 * 160 * 128 * 4)
__global__ __launch_bounds__(256, 1)
void musfuse_kernel(const float* __restrict__ hs, const float* __restrict__ W_x2,
                    const float* __restrict__ x_bias)
{
    extern __shared__ __align__(16) float sm[];
    float* xpT = sm;
    float* wT  = sm + 160 * 128;
    int tid = threadIdx.x;
    int n0 = blockIdx.x * 128;
    int m0 = blockIdx.y * 128;

    for (int u = tid; u < 128 * 40; u += 256) {
        int r = u / 40, q = u % 40;
        float4 v = *(const float4*)(g_xp + (size_t)(m0 + r) * XPP + q * 4);
        xpT[(q*4+0)*128 + r] = v.x; xpT[(q*4+1)*128 + r] = v.y;
        xpT[(q*4+2)*128 + r] = v.z; xpT[(q*4+3)*128 + r] = v.w;
        float4 w = *(const float4*)(W_x2 + (size_t)(n0 + r) * 160 + q * 4);
        wT[(q*4+0)*128 + r] = w.x; wT[(q*4+1)*128 + r] = w.y;
        wT[(q*4+2)*128 + r] = w.z; wT[(q*4+3)*128 + r] = w.w;
    }
    __syncthreads();

    int tx = tid & 15, ty = tid >> 4;
    int col0 = n0 + tx * 8;
    const size_t AS = (size_t)MM * HIDD;

#pragma unroll
    for (int s = 0; s < 5; s++) {
        float acc[8][8];
#pragma unroll
        for (int i = 0; i < 8; i++)
#pragma unroll
            for (int j = 0; j < 8; j++) acc[i][j] = 0.f;

        for (int k = 0; k < 32; k++) {
            int kk = s * 32 + k;
            float4 a0 = *(const float4*)&xpT[kk*128 + ty*8];
            float4 a1 = *(const float4*)&xpT[kk*128 + ty*8 + 4];
            float4 b0 = *(const float4*)&wT [kk*128 + tx*8];
            float4 b1 = *(const float4*)&wT [kk*128 + tx*8 + 4];
            float a[8] = {a0.x,a0.y,a0.z,a0.w,a1.x,a1.y,a1.z,a1.w};
            float b[8] = {b0.x,b0.y,b0.z,b0.w,b1.x,b1.y,b1.z,b1.w};
#pragma unroll
            for (int i = 0; i < 8; i++)
#pragma unroll
                for (int j = 0; j < 8; j++) acc[i][j] += a[i] * b[j];
        }

        float4 bi0 = *(const float4*)(x_bias + s * HIDD + col0);
        float4 bi1 = *(const float4*)(x_bias + s * HIDD + col0 + 4);
        float bias8[8] = {bi0.x,bi0.y,bi0.z,bi0.w,bi1.x,bi1.y,bi1.z,bi1.w};

#pragma unroll
        for (int i = 0; i < 8; i++) {
            int m = m0 + ty * 8 + i;
            int t = m & (TT - 1);
            const float* xr = hs + (size_t)m * HIDD + col0;
            float4 x0 = *(const float4*)xr;
            float4 x1 = *(const float4*)(xr + 4);
            float4 p0 = make_float4(0.f,0.f,0.f,0.f), p1 = p0;
            if (t > 0) {
                p0 = *(const float4*)(xr - HIDD);
                p1 = *(const float4*)(xr - HIDD + 4);
            }
            float xv[8] = {x0.x,x0.y,x0.z,x0.w,x1.x,x1.y,x1.z,x1.w};
            float pv[8] = {p0.x,p0.y,p0.z,p0.w,p1.x,p1.y,p1.z,p1.w};
            float lv[8];
#pragma unroll
            for (int j = 0; j < 8; j++) {
                float mu = acc[i][j] + bias8[j];
                lv[j] = xv[j] + (pv[j] - xv[j]) * mu;
            }
            size_t base = (size_t)m * HIDD + col0;
            __nv_bfloat16 h8[8], l8[8];
#pragma unroll
            for (int j = 0; j < 8; j++) {
                __nv_bfloat16 hh = __float2bfloat16(lv[j]);
                h8[j] = hh;
                l8[j] = __float2bfloat16(lv[j] - __bfloat162float(hh));
            }
            if (s == 1) {
                *(uint4*)(g_mwhi + base) = *(uint4*)h8;
                *(uint4*)(g_mwlo + base) = *(uint4*)l8;
            } else {
                int a = (s == 0) ? 0 : (s - 1);
                *(uint4*)(g_acthi + a * AS + base) = *(uint4*)h8;
                *(uint4*)(g_actlo + a * AS + base) = *(uint4*)l8;
            }
        }
    }
}

// ------------------------ fused prep: lerp0 + all weight hi/lo conversions -----------
#define PRE_L0 (MM*HIDD)
#define PRE_L1 (PRE_L0 + XPP*HIDD)
#define PRE_L2 (PRE_L1 + 128*HIDD)
#define PRE_L3 (PRE_L2 + KDD*HIDD)
#define PRE_L4 (PRE_L3 + KDD*HIDD)
#define PRE_L5 (PRE_L4 + VDD*HIDD)
#define PRE_L6 (PRE_L5 + VDD*HIDD)
#define PRE_L7 (PRE_L6 + HIDD*VDD)
#define PRE_TOT PRE_L7

__device__ __forceinline__ void hilo_store(float x, __nv_bfloat16* hi, __nv_bfloat16* lo, int i)
{
    __nv_bfloat16 h = __float2bfloat16(x);
    hi[i] = h;
    lo[i] = __float2bfloat16(x - __bfloat162float(h));
}

__global__ void prep_kernel(const float* __restrict__ hs, const float* __restrict__ mu0,
                            const float* __restrict__ W_x0, const float* __restrict__ W_w1,
                            const float* __restrict__ W_r,  const float* __restrict__ W_k,
                            const float* __restrict__ W_v,  const float* __restrict__ W_g,
                            const float* __restrict__ W_o)
{
    int i = blockIdx.x * 256 + threadIdx.x;
    if (i < PRE_L0) {
        int m = i >> 10, h = i & 1023;
        int t = m & (TT - 1);
        float x = hs[i];
        float xp = (t > 0) ? hs[i - HIDD] : 0.f;
        float v = x + (xp - x) * mu0[h];
        hilo_store(v, g_xl0hi, g_xl0lo, i);
    } else if (i < PRE_L1) {
        int j = i - PRE_L0;
        float x = ((j >> 10) < 160) ? W_x0[j] : 0.f;
        hilo_store(x, g_wx0hi, g_wx0lo, j);
    } else if (i < PRE_L2) {
        int j = i - PRE_L1;
        float x = ((j >> 10) < GLRK) ? W_w1[j] : 0.f;
        hilo_store(x, g_ww1hi, g_ww1lo, j);
    } else if (i < PRE_L3) {
        int j = i - PRE_L2;  hilo_store(W_r[j], g_wrhi, g_wrlo, j);
    } else if (i < PRE_L4) {
        int j = i - PRE_L3;  hilo_store(W_k[j], g_wkhi, g_wklo, j);
    } else if (i < PRE_L5) {
        int j = i - PRE_L4;  hilo_store(W_v[j], g_wvhi, g_wvlo, j);
    } else if (i < PRE_L6) {
        int j = i - PRE_L5;  hilo_store(W_g[j], g_wghi, g_wglo, j);
    } else {
        int j = i - PRE_L6;  hilo_store(W_o[j], g_wohi, g_wolo, j);
    }
}

__global__ void cterm_kernel(const float* __restrict__ bonus)
{
    int m = blockIdx.x;
    int h = threadIdx.x >> 5, lane = threadIdx.x & 31;
    size_t base = (size_t)m * KDD + h * DKK;
    float s = 0.f;
#pragma unroll
    for (int q = 0; q < 4; q++) {
        int kk = lane + q * 32;
        s += g_r[base + kk] * bonus[h * DKK + kk] * g_k[base + kk];
    }
#pragma unroll
    for (int off = 16; off > 0; off >>= 1) s += __shfl_xor_sync(0xFFFFFFFFu, s, off);
    if (lane == 0) g_c[(size_t)m * NHH + h] = s;
}

// ------------------------ recurrent scan: cp.async 4-batch ring (scalar f32) ---------
#define SC_SLOT 432

__device__ __forceinline__ void scan_issue(uint32_t sbase, int bi, int b, int h,
                                           int vcol, int tid)
{
#pragma unroll
    for (int i = 0; i < 2; i++) {
        int u = tid + i * 256;
        if (u < 420) {
            int step = u / 105, w = u % 105;
            uint32_t st = sbase + (uint32_t)(((bi & 3) * 4 + step) * SC_SLOT) * 4;
            size_t mb = (size_t)(b * TT + bi * 4 + step);
            if (w < 96) {
                int arr = w >> 5, idx = (w & 31) * 4;
                const float* src = (arr == 0 ? g_r : arr == 1 ? g_k : g_ew)
                                 + mb * KDD + h * DKK + idx;
                cpa16(st + (uint32_t)(arr * 128 + idx) * 4, src);
            } else if (w < 104) {
                int idx = (w - 96) * 4;
                cpa16(st + (uint32_t)(384 + idx) * 4, g_v + mb * VDD + vcol + idx);
            } else {
                cpa4(st + 416u * 4, g_c + mb * NHH + h);
            }
        }
    }
    asm volatile("cp.async.commit_group;" ::: "memory");
}

__global__ __launch_bounds__(256, 1)
void scan_kernel()
{
    int ch = blockIdx.x, h = blockIdx.y, b = blockIdx.z;
    int tid = threadIdx.x;
    int kg = tid & 7, jl = tid >> 3;
    int vcol = h * DVV + ch * 32;

    __shared__ __align__(16) float ssc[16 * SC_SLOT];
    uint32_t sbase = s2u(ssc);

    float S[16];
#pragma unroll
    for (int i = 0; i < 16; i++) S[i] = 0.f;

    const int NBATCH = TT / 4;   // 512
    scan_issue(sbase, 0, b, h, vcol, tid);
    scan_issue(sbase, 1, b, h, vcol, tid);
    scan_issue(sbase, 2, b, h, vcol, tid);

    for (int bi = 0; bi < NBATCH; bi++) {
        if (bi < NBATCH - 2)      asm volatile("cp.async.wait_group 2;" ::: "memory");
        else if (bi == NBATCH - 2) asm volatile("cp.async.wait_group 1;" ::: "memory");
        else                       asm volatile("cp.async.wait_group 0;" ::: "memory");
        __syncthreads();

#pragma unroll
        for (int s = 0; s < 4; s++) {
            const float* stg = ssc + ((bi & 3) * 4 + s) * SC_SLOT;
            float vj = stg[384 + jl];
            float cc = stg[416];
            const float4* r4 = (const float4*)(stg + kg * 16);
            const float4* k4 = (const float4*)(stg + 128 + kg * 16);
            const float4* e4 = (const float4*)(stg + 256 + kg * 16);
            float acc = 0.f;
#pragma unroll
            for (int q = 0; q < 4; q++) {
                float4 rv = r4[q], kv = k4[q], ev = e4[q];
                float s0 = S[q*4+0], s1 = S[q*4+1], s2 = S[q*4+2], s3 = S[q*4+3];
                acc += rv.x * s0;  S[q*4+0] = ev.x * s0 + kv.x * vj;
                acc += rv.y * s1;  S[q*4+1] = ev.y * s1 + kv.y * vj;
                acc += rv.z * s2;  S[q*4+2] = ev.z * s2 + kv.z * vj;
                acc += rv.w * s3;  S[q*4+3] = ev.w * s3 + kv.w * vj;
            }
            acc += __shfl_xor_sync(0xFFFFFFFFu, acc, 1);
            acc += __shfl_xor_sync(0xFFFFFFFFu, acc, 2);
            acc += __shfl_xor_sync(0xFFFFFFFFu, acc, 4);
            if (kg == 0) {
                int t = bi * 4 + s;
                g_o[(size_t)(b * TT + t) * VDD + vcol + jl] = acc + cc * vj;
            }
        }
        if (bi + 3 < NBATCH)
            scan_issue(sbase, bi + 3, b, h, vcol, tid);
    }
}

// ------------------------ groupnorm + gate + bf16 split ------------------------------
__global__ void post_kernel(const float* __restrict__ gnw, const float* __restrict__ gnb)
{
    int m = blockIdx.x, h = blockIdx.y;
    int j = threadIdx.x;  // 256
    __shared__ float red[256];
    size_t base = (size_t)m * VDD + h * DVV;
    float val = g_o[base + j];

    red[j] = val; __syncthreads();
    for (int s = 128; s > 0; s >>= 1) { if (j < s) red[j] += red[j + s]; __syncthreads(); }
    float mean = red[0] * (1.f / 256.f);
    __syncthreads();
    float d = val - mean;
    red[j] = d * d; __syncthreads();
    for (int s = 128; s > 0; s >>= 1) { if (j < s) red[j] += red[j + s]; __syncthreads(); }
    float var = red[0] * (1.f / 256.f);

    float nv = d * rsqrtf(var + 1e-5f);
    int col = h * DVV + j;
    float gv = (nv * gnw[col] + gnb[col]) * g_sg[base + j];
    __nv_bfloat16 hh = __float2bfloat16(gv);
    g_gathi[base + j] = hh;
    g_gatlo[base + j] = __float2bfloat16(gv - __bfloat162float(hh));
}

// ------------------------ host launch ------------------------------------------------
extern "C" void kernel_launch(void* const* d_in, const int* in_sizes, int n_in,
                              void* d_out, int out_size)
{
    const float* hs    = (const float*)d_in[0];
    const float* mu0   = (const float*)d_in[1];
    const float* W_x0  = (const float*)d_in[2];
    const float* W_x2  = (const float*)d_in[3];
    const float* x_bias= (const float*)d_in[4];
    const float* W_r   = (const float*)d_in[5];
    const float* W_w1  = (const float*)d_in[6];
    const float* W_w2  = (const float*)d_in[7];
    const float* b_w2  = (const float*)d_in[8];
    const float* W_k   = (const float*)d_in[9];
    const float* W_v   = (const float*)d_in[10];
    const float* W_g   = (const float*)d_in[11];
    const float* bonus = (const float*)d_in[12];
    const float* gnw   = (const float*)d_in[13];
    const float* gnb   = (const float*)d_in[14];
    const float* W_o   = (const float*)d_in[15];
    float* out = (float*)d_out;

    float *xp, *r_, *k_, *ew, *wmid, *v_, *sg;
    cudaGetSymbolAddress((void**)&xp,   g_xp);
    cudaGetSymbolAddress((void**)&r_,   g_r);
    cudaGetSymbolAddress((void**)&k_,   g_k);
    cudaGetSymbolAddress((void**)&ew,   g_ew);
    cudaGetSymbolAddress((void**)&wmid, g_wmid);
    cudaGetSymbolAddress((void**)&v_,   g_v);
    cudaGetSymbolAddress((void**)&sg,   g_sg);

    __nv_bfloat16 *xl0h, *xl0l, *acthi, *actlo, *mwh, *mwl, *gathi, *gatlo;
    __nv_bfloat16 *wx0h, *wx0l, *ww1h, *ww1l;
    __nv_bfloat16 *wrh, *wrl, *wkh, *wkl, *wvh, *wvl, *wgh, *wgl, *woh, *wol;
    cudaGetSymbolAddress((void**)&xl0h, g_xl0hi); cudaGetSymbolAddress((void**)&xl0l, g_xl0lo);
    cudaGetSymbolAddress((void**)&acthi, g_acthi);
    cudaGetSymbolAddress((void**)&actlo, g_actlo);
    cudaGetSymbolAddress((void**)&mwh, g_mwhi);   cudaGetSymbolAddress((void**)&mwl, g_mwlo);
    cudaGetSymbolAddress((void**)&gathi, g_gathi);
    cudaGetSymbolAddress((void**)&gatlo, g_gatlo);
    cudaGetSymbolAddress((void**)&wx0h, g_wx0hi); cudaGetSymbolAddress((void**)&wx0l, g_wx0lo);
    cudaGetSymbolAddress((void**)&ww1h, g_ww1hi); cudaGetSymbolAddress((void**)&ww1l, g_ww1lo);
    cudaGetSymbolAddress((void**)&wrh, g_wrhi);  cudaGetSymbolAddress((void**)&wrl, g_wrlo);
    cudaGetSymbolAddress((void**)&wkh, g_wkhi);  cudaGetSymbolAddress((void**)&wkl, g_wklo);
    cudaGetSymbolAddress((void**)&wvh, g_wvhi);  cudaGetSymbolAddress((void**)&wvl, g_wvlo);
    cudaGetSymbolAddress((void**)&wgh, g_wghi);  cudaGetSymbolAddress((void**)&wgl, g_wglo);
    cudaGetSymbolAddress((void**)&woh, g_wohi);  cudaGetSymbolAddress((void**)&wol, g_wolo);

    cudaFuncSetAttribute(tgemm_kernel<0>, cudaFuncAttributeMaxDynamicSharedMemorySize, HT_SMEM);
    cudaFuncSetAttribute(tgemm_kernel<1>, cudaFuncAttributeMaxDynamicSharedMemorySize, HT_SMEM);
    cudaFuncSetAttribute(tgemm_kernel<3>, cudaFuncAttributeMaxDynamicSharedMemorySize, HT_SMEM);
    cudaFuncSetAttribute(musfuse_kernel,  cudaFuncAttributeMaxDynamicSharedMemorySize, MUS_SMEM);

    // launch 0: fused prep (lerp0 + all weight conversions)
    prep_kernel<<<PRE_TOT/256, 256>>>(hs, mu0, W_x0, W_w1, W_r, W_k, W_v, W_g, W_o);

    // launch 1: xp = tanh(xl0 @ W_x0^T)  (HMMA, N padded to 256)
    tgemm_kernel<1><<<dim3(XPP/128, MM/128), 256, HT_SMEM>>>(xl0h, xl0l, wx0h, wx0l, xp, XPP, HIDD);

    // launch 2: fused 5-slot mus GEMM + lerp + bf16 hi/lo split
    musfuse_kernel<<<dim3(8, MM/128), 256, MUS_SMEM>>>(hs, W_x2, x_bias);

    // launch 3: wmid = tanh(musW @ W_w1^T) (HMMA, N padded to 128)
    tgemm_kernel<1><<<dim3(1, MM/128), 256, HT_SMEM>>>(mwh, mwl, ww1h, ww1l, wmid, 128, HIDD);

    // launch 4: ew = exp(-exp(wmid @ W_w2^T + b)) (SIMT, K=64)
    sgemm_kernel<2><<<dim3(4, MM/128), 256>>>(wmid, 128, W_w2, GLRK, b_w2, ew, KDD, MM, KDD, GLRK);

    // launch 5 (ncu capture target): r projection
    const size_t AS = (size_t)MM * HIDD;
    tgemm_kernel<0><<<dim3(KDD/128, MM/128), 256, HT_SMEM>>>(acthi + 0*AS, actlo + 0*AS, wrh, wrl, r_, KDD, HIDD);
    tgemm_kernel<0><<<dim3(KDD/128, MM/128), 256, HT_SMEM>>>(acthi + 1*AS, actlo + 1*AS, wkh, wkl, k_, KDD, HIDD);
    tgemm_kernel<0><<<dim3(VDD/128, MM/128), 256, HT_SMEM>>>(acthi + 2*AS, actlo + 2*AS, wvh, wvl, v_, VDD, HIDD);
    tgemm_kernel<3><<<dim3(VDD/128, MM/128), 256, HT_SMEM>>>(acthi + 3*AS, actlo + 3*AS, wgh, wgl, sg, VDD, HIDD);

    // bonus scalar
    cterm_kernel<<<MM, 128>>>(bonus);

    // recurrent scan (cp.async ring, scalar f32)
    scan_kernel<<<dim3(8, NHH, BB), 256>>>();

    // groupnorm + silu gate -> bf16 hi/lo
    post_kernel<<<dim3(MM, NHH), 256>>>(gnw, gnb);

    // out = gated @ W_o^T
    tgemm_kernel<0><<<dim3(HIDD/128, MM/128), 256, HT_SMEM>>>(gathi, gatlo, woh, wol, out, HIDD, VDD);
}